// round 6
// baseline (speedup 1.0000x reference)
#include <cuda_runtime.h>

// out[s,b,d] = x0*Wxy[d,0] + x1*Wxy[d,1] + x2*Wseg[d] + b_xy[d] + b_seg[d] + pe[s,d]
// Shapes: x[256,256,3], W_xy[1024,2], b_xy[1024], W_seg[1024,1], b_seg[1024],
//         pe[256,1,1024], out[256,256,1024] fp32.  HBM-write-path bound.
//
// R6 changes vs R3/R4 (kernel ~40-41us pinned, DRAM 64-67%, occ 86%):
//  - SINGLE-WAVE launch: BCHUNK=64 -> 1024 blocks; at 8 CTAs/SM (1184 capacity)
//    every block is resident in wave 1 -> zero wave transitions, no partial-wave
//    tail (was 3.46 waves = ~2.5 transitions + tail ~ 4-6us)
//  - keep __stcs (evidence: beats write-back across rounds)
//  - keep one-shot smem float4 staging (single barrier per block)

#define D_MODEL 1024
#define SEQ     256
#define BATCH   256
#define BCHUNK  64   // batch elements per block -> grid (4,256) = 1024 blocks

__global__ __launch_bounds__(256, 8)
void pe_fused_kernel(const float* __restrict__ x,
                     const float* __restrict__ W_xy,
                     const float* __restrict__ b_xy,
                     const float* __restrict__ W_seg,
                     const float* __restrict__ b_seg,
                     const float* __restrict__ pe,
                     float* __restrict__ out)
{
    __shared__ float4 xs4[BCHUNK];     // {x0, x1, x2, pad} per batch row

    const int t  = threadIdx.x;        // 0..255, owns d = 4t..4t+3
    const int s  = blockIdx.y;         // 0..255
    const int b0 = blockIdx.x * BCHUNK;
    const int d  = t << 2;

    // stage x for this (s, b-chunk): 64 rows, one padded float4 each
    if (t < BCHUNK) {
        const float* xp = x + (size_t)(s * BATCH + b0 + t) * 3;
        xs4[t] = make_float4(xp[0], xp[1], xp[2], 0.0f);
    }

    // --- per-d constants, loaded once per block into registers ---
    // W_xy is [D,2] interleaved: deswizzle two float4s into wx / wy lanes.
    const float4 w0 = *reinterpret_cast<const float4*>(W_xy + 2 * d);
    const float4 w1 = *reinterpret_cast<const float4*>(W_xy + 2 * d + 4);
    const float4 wx = make_float4(w0.x, w0.z, w1.x, w1.z);
    const float4 wy = make_float4(w0.y, w0.w, w1.y, w1.w);
    const float4 ws = *reinterpret_cast<const float4*>(W_seg + d);

    const float4 bx = *reinterpret_cast<const float4*>(b_xy + d);
    const float4 bs = *reinterpret_cast<const float4*>(b_seg + d);
    const float4 p  = *reinterpret_cast<const float4*>(pe + (size_t)s * D_MODEL + d);

    const float4 c = make_float4(p.x + bx.x + bs.x,
                                 p.y + bx.y + bs.y,
                                 p.z + bx.z + bs.z,
                                 p.w + bx.w + bs.w);

    float* op = out + ((size_t)(s * BATCH + b0)) * D_MODEL + d;

    __syncthreads();

    #pragma unroll 8
    for (int i = 0; i < BCHUNK; ++i) {
        // single broadcast LDS.128 (conflict-free)
        const float4 xv = xs4[i];

        float4 o;
        o.x = fmaf(xv.x, wx.x, fmaf(xv.y, wy.x, fmaf(xv.z, ws.x, c.x)));
        o.y = fmaf(xv.x, wx.y, fmaf(xv.y, wy.y, fmaf(xv.z, ws.y, c.y)));
        o.z = fmaf(xv.x, wx.z, fmaf(xv.y, wy.z, fmaf(xv.z, ws.z, c.z)));
        o.w = fmaf(xv.x, wx.w, fmaf(xv.y, wy.w, fmaf(xv.z, ws.w, c.w)));

        // streaming store: write-once, evict-first
        __stcs(reinterpret_cast<float4*>(op + (size_t)i * D_MODEL), o);
    }
}

extern "C" void kernel_launch(void* const* d_in, const int* in_sizes, int n_in,
                              void* d_out, int out_size)
{
    const float* x     = (const float*)d_in[0];
    const float* W_xy  = (const float*)d_in[1];
    const float* b_xy  = (const float*)d_in[2];
    const float* W_seg = (const float*)d_in[3];
    const float* b_seg = (const float*)d_in[4];
    const float* pe    = (const float*)d_in[5];
    float* out = (float*)d_out;

    dim3 grid(BATCH / BCHUNK, SEQ);   // (4, 256) = 1024 blocks, single wave @ occ 8
    dim3 block(256);
    pe_fused_kernel<<<grid, block>>>(x, W_xy, b_xy, W_seg, b_seg, pe, out);
}

// round 10
// speedup vs baseline: 1.0107x; 1.0107x over previous
#include <cuda_runtime.h>

// out[s,b,d] = x0*Wxy[d,0] + x1*Wxy[d,1] + x2*Wseg[d] + b_xy[d] + b_seg[d] + pe[s,d]
// Shapes: x[256,256,3], W_xy[1024,2], b_xy[1024], W_seg[1024,1], b_seg[1024],
//         pe[256,1,1024], out[256,256,1024] fp32.  DRAM-write-path bound.
//
// R7 change vs R2/R3 (kernel pinned 40-41us; bench 41.7-43.0):
//  - __stwt write-through stores: no dirty L2 accumulation between graph
//    replays -> next replay's stores don't stall on evicting previous
//    replay's dirty output lines. Targets the bench-vs-ncu gap, not kernel dur.
//  - otherwise best-known config: BCHUNK=16, occ 8, one-shot smem staging.

#define D_MODEL 1024
#define SEQ     256
#define BATCH   256
#define BCHUNK  16   // batch elements per block -> grid (16,256) = 4096 blocks

__global__ __launch_bounds__(256, 8)
void pe_fused_kernel(const float* __restrict__ x,
                     const float* __restrict__ W_xy,
                     const float* __restrict__ b_xy,
                     const float* __restrict__ W_seg,
                     const float* __restrict__ b_seg,
                     const float* __restrict__ pe,
                     float* __restrict__ out)
{
    __shared__ float4 xs4[BCHUNK];     // {x0, x1, x2, pad} per batch row

    const int t  = threadIdx.x;        // 0..255, owns d = 4t..4t+3
    const int s  = blockIdx.y;         // 0..255
    const int b0 = blockIdx.x * BCHUNK;
    const int d  = t << 2;

    // stage x for this (s, b-chunk)
    if (t < BCHUNK) {
        const float* xp = x + (size_t)(s * BATCH + b0 + t) * 3;
        xs4[t] = make_float4(xp[0], xp[1], xp[2], 0.0f);
    }

    // --- per-d constants, loaded once per block into registers ---
    // W_xy is [D,2] interleaved: deswizzle two float4s into wx / wy lanes.
    const float4 w0 = *reinterpret_cast<const float4*>(W_xy + 2 * d);
    const float4 w1 = *reinterpret_cast<const float4*>(W_xy + 2 * d + 4);
    const float4 wx = make_float4(w0.x, w0.z, w1.x, w1.z);
    const float4 wy = make_float4(w0.y, w0.w, w1.y, w1.w);
    const float4 ws = *reinterpret_cast<const float4*>(W_seg + d);

    const float4 bx = *reinterpret_cast<const float4*>(b_xy + d);
    const float4 bs = *reinterpret_cast<const float4*>(b_seg + d);
    const float4 p  = *reinterpret_cast<const float4*>(pe + (size_t)s * D_MODEL + d);

    const float4 c = make_float4(p.x + bx.x + bs.x,
                                 p.y + bx.y + bs.y,
                                 p.z + bx.z + bs.z,
                                 p.w + bx.w + bs.w);

    float* op = out + ((size_t)(s * BATCH + b0)) * D_MODEL + d;

    __syncthreads();

    #pragma unroll
    for (int i = 0; i < BCHUNK; ++i) {
        // single broadcast LDS.128 (conflict-free)
        const float4 xv = xs4[i];

        float4 o;
        o.x = fmaf(xv.x, wx.x, fmaf(xv.y, wy.x, fmaf(xv.z, ws.x, c.x)));
        o.y = fmaf(xv.x, wx.y, fmaf(xv.y, wy.y, fmaf(xv.z, ws.y, c.y)));
        o.z = fmaf(xv.x, wx.z, fmaf(xv.y, wy.z, fmaf(xv.z, ws.z, c.z)));
        o.w = fmaf(xv.x, wx.w, fmaf(xv.y, wy.w, fmaf(xv.z, ws.w, c.w)));

        // write-through store: no dirty L2 lines, steady DRAM write stream
        __stwt(reinterpret_cast<float4*>(op + (size_t)i * D_MODEL), o);
    }
}

extern "C" void kernel_launch(void* const* d_in, const int* in_sizes, int n_in,
                              void* d_out, int out_size)
{
    const float* x     = (const float*)d_in[0];
    const float* W_xy  = (const float*)d_in[1];
    const float* b_xy  = (const float*)d_in[2];
    const float* W_seg = (const float*)d_in[3];
    const float* b_seg = (const float*)d_in[4];
    const float* pe    = (const float*)d_in[5];
    float* out = (float*)d_out;

    dim3 grid(BATCH / BCHUNK, SEQ);   // (16, 256) = 4096 blocks
    dim3 block(256);
    pe_fused_kernel<<<grid, block>>>(x, W_xy, b_xy, W_seg, b_seg, pe, out);
}